// round 6
// baseline (speedup 1.0000x reference)
#include <cuda_runtime.h>
#include <math.h>

// x: [64, 3, 512, 512] fp32. Per 8x8 block compute |FFT2| at bins
// (0,1),(1,0),(1,1),(2,2),(3,3),(4,4), mean over the 64x64 block grid,
// output [192, 6].
//
// R3 change: 8 stripe-CTAs per plane (1536 CTAs total) for SM load balance;
// last-arriving stripe CTA per plane reduces partials and writes out.
// Replay-safe: arrival counters self-reset; partials rewritten each replay.

#define PLANE_ELEMS (512 * 512)
#define NBLOCKS_PER_PLANE 4096   // 64 x 64 blocks of 8x8
#define NSTRIPES 8               // stripes per plane (8 block-rows each)
#define THREADS 512

__device__ float    g_partial[192][NSTRIPES][6];
__device__ unsigned g_count[192];   // zero-initialized at load; self-resetting

__global__ __launch_bounds__(THREADS, 2)
void dct_bands_kernel(const float* __restrict__ x, float* __restrict__ out) {
    const int plane  = blockIdx.x >> 3;           // 0..191
    const int stripe = blockIdx.x & 7;            // 0..7
    const float* __restrict__ base = x + (size_t)plane * PLANE_ELEMS;
    const int tid = threadIdx.x;

    constexpr float S = 0.70710678118654752440f;
    const float C45[8]  = {1.f,  S, 0.f, -S, -1.f, -S, 0.f,  S};
    const float S45[8]  = {0.f,  S, 1.f,  S,  0.f, -S, -1.f, -S};
    const float C90[8]  = {1.f, 0.f, -1.f, 0.f, 1.f, 0.f, -1.f, 0.f};
    const float S90[8]  = {0.f, 1.f, 0.f, -1.f, 0.f, 1.f, 0.f, -1.f};
    const float C135[8] = {1.f, -S, 0.f,  S, -1.f,  S, 0.f, -S};
    const float S135[8] = {0.f,  S, -1.f, S,  0.f, -S, 1.f, -S};

    // One tile per thread: stripe covers 8 block-rows x 64 block-cols = 512 tiles.
    const int gi = (stripe << 3) + (tid >> 6);    // global block row
    const int gj = tid & 63;                      // block col
    const float* bp = base + ((size_t)(gi << 3) << 9) + (gj << 3);

    float a01r = 0.f, a01i = 0.f;
    float a10r = 0.f, a10i = 0.f;
    float a11r = 0.f, a11i = 0.f;
    float a22r = 0.f, a22i = 0.f;
    float a33r = 0.f, a33i = 0.f;
    float a44  = 0.f;

    #pragma unroll
    for (int m = 0; m < 8; ++m) {
        const float4 lo = *reinterpret_cast<const float4*>(bp + m * 512);
        const float4 hi = *reinterpret_cast<const float4*>(bp + m * 512 + 4);
        const float x0 = lo.x, x1 = lo.y, x2 = lo.z, x3 = lo.w;
        const float x4 = hi.x, x5 = hi.y, x6 = hi.z, x7 = hi.w;

        const float p  = x1 - x3 - x5 + x7;
        const float q  = x1 + x3 - x5 - x7;
        const float e0 = x0 - x4;
        const float e2 = x2 - x6;

        const float r0  = x0 + x1 + x2 + x3 + x4 + x5 + x6 + x7;
        const float re1 = e0 + p * S;
        const float im1 = -(q * S + e2);
        const float re2 = x0 - x2 + x4 - x6;
        const float im2 = -(x1 - x3 + x5 - x7);
        const float re3 = e0 - p * S;
        const float im3 = -(q * S - e2);
        const float r4  = x0 - x1 + x2 - x3 + x4 - x5 + x6 - x7;

        const float w1r = C45[m],  w1i = -S45[m];
        const float w2r = C90[m],  w2i = -S90[m];
        const float w3r = C135[m], w3i = -S135[m];

        a01r += re1;                  a01i += im1;
        a10r += r0 * w1r;             a10i += r0 * w1i;
        a11r += re1 * w1r - im1 * w1i;
        a11i += re1 * w1i + im1 * w1r;
        a22r += re2 * w2r - im2 * w2i;
        a22i += re2 * w2i + im2 * w2r;
        a33r += re3 * w3r - im3 * w3i;
        a33i += re3 * w3i + im3 * w3r;
        a44  += (m & 1) ? -r4 : r4;
    }

    float v[6];
    v[0] = sqrtf(a01r * a01r + a01i * a01i);
    v[1] = sqrtf(a10r * a10r + a10i * a10i);
    v[2] = sqrtf(a11r * a11r + a11i * a11i);
    v[3] = sqrtf(a22r * a22r + a22i * a22i);
    v[4] = sqrtf(a33r * a33r + a33i * a33i);
    v[5] = fabsf(a44);

    // ---- CTA reduction: 512 threads x 6 floats ----
    #pragma unroll
    for (int j = 0; j < 6; ++j) {
        #pragma unroll
        for (int o = 16; o > 0; o >>= 1)
            v[j] += __shfl_down_sync(0xffffffffu, v[j], o);
    }

    __shared__ float red[16][6];
    __shared__ int   s_last;
    const int lane = tid & 31, warp = tid >> 5;
    if (lane == 0) {
        #pragma unroll
        for (int j = 0; j < 6; ++j) red[warp][j] = v[j];
    }
    __syncthreads();

    if (tid < 6) {
        float t = 0.f;
        #pragma unroll
        for (int w = 0; w < 16; ++w) t += red[w][tid];
        g_partial[plane][stripe][tid] = t;
        __threadfence();              // make partial visible device-wide
    }
    __syncthreads();

    if (tid == 0) {
        unsigned old = atomicAdd(&g_count[plane], 1u);
        s_last = (old == NSTRIPES - 1);
    }
    __syncthreads();

    if (s_last) {
        if (tid < 6) {
            __threadfence();          // acquire: order partial reads after count
            float t = 0.f;
            #pragma unroll
            for (int s = 0; s < NSTRIPES; ++s) t += g_partial[plane][s][tid];
            out[plane * 6 + tid] = t * (1.0f / (float)NBLOCKS_PER_PLANE);
        }
        __syncthreads();
        if (tid == 0) g_count[plane] = 0;   // self-reset for next graph replay
    }
}

extern "C" void kernel_launch(void* const* d_in, const int* in_sizes, int n_in,
                              void* d_out, int out_size) {
    const float* x = (const float*)d_in[0];
    float* out = (float*)d_out;
    const int n_planes = in_sizes[0] / PLANE_ELEMS;   // 192
    dct_bands_kernel<<<n_planes * NSTRIPES, THREADS>>>(x, out);
}

// round 7
// speedup vs baseline: 1.0566x; 1.0566x over previous
#include <cuda_runtime.h>
#include <math.h>

// x: [64, 3, 512, 512] fp32. Per 8x8 block compute |FFT2| at bins
// (0,1),(1,0),(1,1),(2,2),(3,3),(4,4), mean over the 64x64 block grid,
// output [192, 6].
//
// R6: 2 half-plane CTAs per plane (384 CTAs x 256 thr), 8 mainloop
// iterations per thread (long-lived CTAs like R0), single wave,
// max/avg per-SM load ratio 1.16 (vs 1.54 at grid=192).

#define PLANE_ELEMS (512 * 512)
#define NBLOCKS_PER_PLANE 4096   // 64 x 64 blocks of 8x8
#define THREADS 256
#define ITERS 8                  // 2048 tiles per half-plane / 256 threads

__device__ float    g_partial[192][2][6];
__device__ unsigned g_count[192];   // zero-initialized at load; self-resetting

__global__ __launch_bounds__(THREADS, 4)
void dct_bands_kernel(const float* __restrict__ x, float* __restrict__ out) {
    const int plane  = blockIdx.x >> 1;           // 0..191
    const int half   = blockIdx.x & 1;            // 0..1
    const float* __restrict__ base = x + (size_t)plane * PLANE_ELEMS;
    const int tid = threadIdx.x;

    constexpr float S = 0.70710678118654752440f;
    const float C45[8]  = {1.f,  S, 0.f, -S, -1.f, -S, 0.f,  S};
    const float S45[8]  = {0.f,  S, 1.f,  S,  0.f, -S, -1.f, -S};
    const float C90[8]  = {1.f, 0.f, -1.f, 0.f, 1.f, 0.f, -1.f, 0.f};
    const float S90[8]  = {0.f, 1.f, 0.f, -1.f, 0.f, 1.f, 0.f, -1.f};
    const float C135[8] = {1.f, -S, 0.f,  S, -1.f,  S, 0.f, -S};
    const float S135[8] = {0.f,  S, -1.f, S,  0.f, -S, 1.f, -S};

    float sum0 = 0.f, sum1 = 0.f, sum2 = 0.f, sum3 = 0.f, sum4 = 0.f, sum5 = 0.f;

    #pragma unroll 1
    for (int k = 0; k < ITERS; ++k) {
        const int t  = (k << 8) + tid;            // tile idx within half (0..2047)
        const int gi = (half << 5) + (t >> 6);    // global block row (0..63)
        const int gj = t & 63;                    // block col
        const float* bp = base + ((size_t)(gi << 3) << 9) + (gj << 3);

        float a01r = 0.f, a01i = 0.f;
        float a10r = 0.f, a10i = 0.f;
        float a11r = 0.f, a11i = 0.f;
        float a22r = 0.f, a22i = 0.f;
        float a33r = 0.f, a33i = 0.f;
        float a44  = 0.f;

        #pragma unroll
        for (int m = 0; m < 8; ++m) {
            const float4 lo = *reinterpret_cast<const float4*>(bp + m * 512);
            const float4 hi = *reinterpret_cast<const float4*>(bp + m * 512 + 4);
            const float x0 = lo.x, x1 = lo.y, x2 = lo.z, x3 = lo.w;
            const float x4 = hi.x, x5 = hi.y, x6 = hi.z, x7 = hi.w;

            const float p  = x1 - x3 - x5 + x7;
            const float q  = x1 + x3 - x5 - x7;
            const float e0 = x0 - x4;
            const float e2 = x2 - x6;

            const float r0  = x0 + x1 + x2 + x3 + x4 + x5 + x6 + x7;
            const float re1 = e0 + p * S;
            const float im1 = -(q * S + e2);
            const float re2 = x0 - x2 + x4 - x6;
            const float im2 = -(x1 - x3 + x5 - x7);
            const float re3 = e0 - p * S;
            const float im3 = -(q * S - e2);
            const float r4  = x0 - x1 + x2 - x3 + x4 - x5 + x6 - x7;

            const float w1r = C45[m],  w1i = -S45[m];
            const float w2r = C90[m],  w2i = -S90[m];
            const float w3r = C135[m], w3i = -S135[m];

            a01r += re1;                  a01i += im1;
            a10r += r0 * w1r;             a10i += r0 * w1i;
            a11r += re1 * w1r - im1 * w1i;
            a11i += re1 * w1i + im1 * w1r;
            a22r += re2 * w2r - im2 * w2i;
            a22i += re2 * w2i + im2 * w2r;
            a33r += re3 * w3r - im3 * w3i;
            a33i += re3 * w3i + im3 * w3r;
            a44  += (m & 1) ? -r4 : r4;
        }

        sum0 += sqrtf(a01r * a01r + a01i * a01i);
        sum1 += sqrtf(a10r * a10r + a10i * a10i);
        sum2 += sqrtf(a11r * a11r + a11i * a11i);
        sum3 += sqrtf(a22r * a22r + a22i * a22i);
        sum4 += sqrtf(a33r * a33r + a33i * a33i);
        sum5 += fabsf(a44);
    }

    // ---- CTA reduction: 256 threads x 6 floats ----
    float v[6] = {sum0, sum1, sum2, sum3, sum4, sum5};

    #pragma unroll
    for (int j = 0; j < 6; ++j) {
        #pragma unroll
        for (int o = 16; o > 0; o >>= 1)
            v[j] += __shfl_down_sync(0xffffffffu, v[j], o);
    }

    __shared__ float red[8][6];
    __shared__ int   s_last;
    const int lane = tid & 31, warp = tid >> 5;
    if (lane == 0) {
        #pragma unroll
        for (int j = 0; j < 6; ++j) red[warp][j] = v[j];
    }
    __syncthreads();

    if (tid < 6) {
        float t = 0.f;
        #pragma unroll
        for (int w = 0; w < 8; ++w) t += red[w][tid];
        g_partial[plane][half][tid] = t;
        __threadfence();              // release partials device-wide
    }
    __syncthreads();

    if (tid == 0) {
        unsigned old = atomicAdd(&g_count[plane], 1u);
        s_last = (old == 1u);
    }
    __syncthreads();

    if (s_last) {
        if (tid < 6) {
            __threadfence();          // acquire
            float t = g_partial[plane][0][tid] + g_partial[plane][1][tid];
            out[plane * 6 + tid] = t * (1.0f / (float)NBLOCKS_PER_PLANE);
        }
        __syncthreads();
        if (tid == 0) g_count[plane] = 0;   // self-reset for next graph replay
    }
}

extern "C" void kernel_launch(void* const* d_in, const int* in_sizes, int n_in,
                              void* d_out, int out_size) {
    const float* x = (const float*)d_in[0];
    float* out = (float*)d_out;
    const int n_planes = in_sizes[0] / PLANE_ELEMS;   // 192
    dct_bands_kernel<<<n_planes * 2, THREADS>>>(x, out);
}